// round 8
// baseline (speedup 1.0000x reference)
#include <cuda_runtime.h>
#include <math.h>

#define NPART 4096
#define MAXNB 48

// ---------------- device scratch (no allocations allowed) ----------------
__device__ float2         g_p0[NPART];            // pos + trans (collision input)
__device__ unsigned short g_nb16[NPART * MAXNB];  // candidate lists (uint16 idx, 96B rows)
__device__ int            g_ncnt[NPART];

// ---------------- constants (match reference float32 semantics) ----------
#define PI_F      3.1415927410125732f
#define TWO_PI_F  6.2831854820251465f

__device__ __forceinline__ float wrapf(float diff) {
    // matches: where(diff <= -pi, mod(diff, pi), diff); then -2pi if >= pi
    if (diff <= -PI_F) {
        float m = fmodf(diff, PI_F);       // C fmod: sign of dividend
        if (m < 0.0f) m += PI_F;           // -> pythonic mod in [0, pi)
        diff = m;
    }
    if (diff >= PI_F) diff -= TWO_PI_F;
    return diff;
}

// ---------------- K1: N^2 pair pass + per-particle epilogue ----------------
// One warp per particle. 128 blocks x 32 warps = 4096 particles.
__global__ void __launch_bounds__(1024) k_main(
    const float* __restrict__ pre, const float* __restrict__ pim,
    const float* __restrict__ ore, const float* __restrict__ oim,
    const float* __restrict__ deltas, const float* __restrict__ rotn,
    const float* __restrict__ tnr, const float* __restrict__ tni,
    float* __restrict__ out)
{
    const float RO_RC2 = (float)(2.815e-5 * 2.815e-5);   // (RO+RC)^2
    const float RR2    = (float)(8.0e-6 * 8.0e-6);       // RR^2
    const float NB2    = (float)(2.52e-5 * 2.52e-5);     // (8*RC)^2 candidate radius

    __shared__ float2 spos[NPART];   // 32 KB: whole system
    __shared__ float  swx[32], swy[32];
    __shared__ float2 smean;

    int t    = threadIdx.x;
    int warp = t >> 5;
    int lane = t & 31;

    // stage positions + partial mean sums
    float ax = 0.f, ay = 0.f;
#pragma unroll
    for (int k = 0; k < 4; k++) {
        int idx = t + 1024 * k;
        float x = pre[idx], y = pim[idx];
        spos[idx] = make_float2(x, y);
        ax += x; ay += y;
    }
#pragma unroll
    for (int o = 16; o > 0; o >>= 1) {
        ax += __shfl_down_sync(0xffffffffu, ax, o);
        ay += __shfl_down_sync(0xffffffffu, ay, o);
    }
    if (lane == 0) { swx[warp] = ax; swy[warp] = ay; }
    __syncthreads();
    if (warp == 0) {
        float bx = swx[lane], by = swy[lane];
#pragma unroll
        for (int o = 16; o > 0; o >>= 1) {
            bx += __shfl_down_sync(0xffffffffu, bx, o);
            by += __shfl_down_sync(0xffffffffu, by, o);
        }
        if (lane == 0) smean = make_float2(bx * (1.0f / 4096.0f), by * (1.0f / 4096.0f));
    }
    __syncthreads();

    int i = blockIdx.x * 32 + warp;
    float2 pi_ = spos[i];
    float  orx = __ldg(&ore[i]), ory = __ldg(&oim[i]);

    float osr = 0.f, osi = 0.f, sx = 0.f, sy = 0.f;
    int nr = 0, cnt = 0;
    unsigned lmask = (1u << lane) - 1u;
    const float4* sp4 = reinterpret_cast<const float4*>(spos);

#pragma unroll 4
    for (int jj = lane; jj < NPART / 2; jj += 32) {
        float4 v = sp4[jj];                    // particles 2jj, 2jj+1
        int jA = 2 * jj, jB = 2 * jj + 1;
        float dxA = v.x - pi_.x, dyA = v.y - pi_.y;
        float dxB = v.z - pi_.x, dyB = v.w - pi_.y;
        float d2A = fmaf(dxA, dxA, dyA * dyA);
        float d2B = fmaf(dxB, dxB, dyB * dyB);
        bool roA = (d2A <= RO_RC2), roB = (d2B <= RO_RC2);
        unsigned mro = __ballot_sync(0xffffffffu, roA || roB);
        if (mro) {   // rare branch (~9% of iterations), warp-uniform
            bool nbA = roA && (d2A <= NB2) && (jA != i);
            bool nbB = roB && (d2B <= NB2) && (jB != i);
            unsigned mA = __ballot_sync(0xffffffffu, nbA);
            unsigned mB = __ballot_sync(0xffffffffu, nbB);
            if (nbA) {
                int idx = cnt + __popc(mA & lmask);
                if (idx < MAXNB) g_nb16[i * MAXNB + idx] = (unsigned short)jA;
            }
            cnt += __popc(mA);
            if (nbB) {
                int idx = cnt + __popc(mB & lmask);
                if (idx < MAXNB) g_nb16[i * MAXNB + idx] = (unsigned short)jB;
            }
            cnt += __popc(mB);
            if (roA) {
                float ojx = __ldg(&ore[jA]), ojy = __ldg(&oim[jA]);
                osr += ojx; osi += ojy;
                if (d2A <= RR2 && jA != i) {
                    // |wrap(ang_i-ang_j)| < pi/2  <=>  dot(ori_i, ori_j) > 0
                    if (orx * ojx + ory * ojy > 0.0f) { nr += 1; sx += v.x; sy += v.y; }
                }
            }
            if (roB) {
                float ojx = __ldg(&ore[jB]), ojy = __ldg(&oim[jB]);
                osr += ojx; osi += ojy;
                if (d2B <= RR2 && jB != i) {
                    if (orx * ojx + ory * ojy > 0.0f) { nr += 1; sx += v.z; sy += v.w; }
                }
            }
        }
    }

    // warp reduction
#pragma unroll
    for (int o = 16; o > 0; o >>= 1) {
        osr += __shfl_down_sync(0xffffffffu, osr, o);
        osi += __shfl_down_sync(0xffffffffu, osi, o);
        sx  += __shfl_down_sync(0xffffffffu, sx,  o);
        sy  += __shfl_down_sync(0xffffffffu, sy,  o);
        nr  += __shfl_down_sync(0xffffffffu, nr,  o);
    }

    if (lane == 0) {
        g_ncnt[i] = (cnt < MAXNB) ? cnt : MAXNB;

        float angi = atan2f(ory, orx);
        float2 mean = smean;
        float invn = 1.0f / fmaxf((float)nr, 1.0f);
        float sgn  = (nr > 0) ? 1.0f : 0.0f;
        float Sx = sx * invn - pi_.x * sgn;
        float Sy = sy * invn - pi_.y * sgn;
        float dxr = -Sx, dyr = -Sy;

        float Psx = mean.x - pi_.x;
        float Psy = mean.y - pi_.y;

        float del = deltas[i];
        float cd, sd; sincosf(del, &sd, &cd);
        float lx = Psx * cd - Psy * sd;            // Ps * exp(+i delta)
        float ly = Psx * sd + Psy * cd;
        float rx = Psx * cd + Psy * sd;            // Ps * exp(-i delta)
        float ry = Psy * cd - Psx * sd;

        float no  = fmaxf(sqrtf(osr * osr + osi * osi), 1e-14f);
        float nl  = fmaxf(sqrtf(lx * lx + ly * ly), 1e-14f);
        float nrt = fmaxf(sqrtf(rx * rx + ry * ry), 1e-14f);
        float csl = (lx * osr + ly * osi) / (nl * no);
        float csr = (rx * osr + ry * osi) / (nrt * no);
        float bx = (csl >= csr) ? lx : rx;
        float by = (csl >= csr) ? ly : ry;

        bool hasrep = (dxr * dxr + dyr * dyr) > 0.0f;
        float aa  = hasrep ? atan2f(dyr, dxr) : atan2f(by, bx);
        float att = wrapf(aa - angi);

        float theta = 0.014f * sinf(att)
                    + (rotn[i] * 0.074833147735478508f) * 0.44721359549995793f;
        float cr, sr; sincosf(theta, &sr, &cr);
        float nor = orx * cr - ory * sr;           // new_ori = ori * rot
        float noi = orx * sr + ory * cr;

        float tnx = ((tnr[i] * 0.70710678118654752f) * 1.6733200530681511e-7f)
                    * 0.44721359549995793f;
        float tny = ((tni[i] * 0.70710678118654752f) * 1.6733200530681511e-7f)
                    * 0.44721359549995793f;
        float trx = 1e-7f * orx + tnx;             // DT*VEL*ori + tnoise*sqrt(DT)
        float try_ = 1e-7f * ory + tny;

        g_p0[i] = make_float2(pi_.x + trx, pi_.y + try_);

        out[ 8192 + 2 * i]     = nor;  out[ 8192 + 2 * i + 1] = noi;  // new_ori
        out[16384 + 2 * i]     = osr;  out[16384 + 2 * i + 1] = osi;  // osum
        out[24576 + 2 * i]     = lx;   out[24576 + 2 * i + 1] = ly;   // left
        out[32768 + 2 * i]     = rx;   out[32768 + 2 * i + 1] = ry;   // right
    }
}

// ---------------- K2: collision solve, queue-compacted active set ----------
// One block. Active particles are compacted into a queue each iteration and
// distributed round-robin across all 1024 threads (load-balanced). Queue order
// is nondeterministic (atomicAdd slot allocation) but each particle's move is
// computed with a deterministic neighbor order, so results are bit-identical.
__global__ void __launch_bounds__(1024) k_collide(float* __restrict__ out) {
    __shared__ float2         sp[NPART];      // 32 KB positions
    __shared__ unsigned short queue[NPART];   // 8 KB active-particle queue
    __shared__ unsigned char  mark[NPART];    // 4 KB epoch stamps
    __shared__ int            qcnt;

    int t = threadIdx.x;
    int lane = t & 31;
    unsigned lmask = (1u << lane) - 1u;

#pragma unroll
    for (int k = 0; k < 4; k++) {
        int i = t + 1024 * k;
        sp[i] = g_p0[i];
        mark[i] = 0;
    }
    __syncthreads();

    const float C2  = (float)(6.3e-6 * 6.3e-6);   // (2*RC)^2
    const float TRC = 6.615e-6f;                  // 2.1*RC

    int nact = NPART;                             // iteration 0: identity queue

    for (int it = 0; it < 30; it++) {
        // ---- compute phase (reads sp; moves stay in registers) ----
        bool moved_any = false;
        int   mvi[4]; float mvx[4], mvy[4];
        int nmv = 0;
        for (int s = t; s < nact; s += 1024) {
            int i = (it == 0) ? s : (int)queue[s];
            int c = g_ncnt[i];                    // L1-hot
            if (c > 0) {
                float2 p = sp[i];
                float ax = 0.f, ay = 0.f;
                bool m = false;
                const unsigned short* nb = &g_nb16[i * MAXNB];
                for (int q = 0; q < c; q++) {
                    float2 pj = sp[nb[q]];
                    float dx = pj.x - p.x;
                    float dy = pj.y - p.y;
                    float d2 = dx * dx + dy * dy;
                    if (d2 <= C2) {
                        float dd = sqrtf(d2);
                        float sc = (TRC - dd) * 0.5f / dd;
                        ax += dx * sc; ay += dy * sc;
                        m = true;
                    }
                }
                if (m) {
                    mvi[nmv] = i;
                    mvx[nmv] = p.x - ax;          // new position
                    mvy[nmv] = p.y - ay;
                    nmv++;
                    moved_any = true;
                }
            }
        }
        int tot = __syncthreads_count(moved_any ? 1 : 0);   // all sp reads done
        if (tot == 0) break;          // fixed point: matches reference cont flag

        // ---- apply + stamp phase ----
        unsigned char epn = (unsigned char)(it + 1);
        for (int r = 0; r < nmv; r++) {
            int i = mvi[r];
            sp[i] = make_float2(mvx[r], mvy[r]);
            mark[i] = epn;
            int c = g_ncnt[i];
            const unsigned short* nb = &g_nb16[i * MAXNB];
            for (int q = 0; q < c; q++) mark[nb[q]] = epn;  // benign same-value races
        }
        if (t == 0) qcnt = 0;
        __syncthreads();              // marks + qcnt reset visible

        // ---- compaction phase: build next queue (any order OK) ----
#pragma unroll
        for (int k = 0; k < 4; k++) {
            int i = t + 1024 * k;
            bool a = (mark[i] == epn);
            unsigned mb = __ballot_sync(0xffffffffu, a);
            if (mb) {
                int leader = __ffs(mb) - 1;
                int base = 0;
                if (lane == leader) base = atomicAdd(&qcnt, __popc(mb));
                base = __shfl_sync(0xffffffffu, base, leader);
                if (a) queue[base + __popc(mb & lmask)] = (unsigned short)i;
            }
        }
        __syncthreads();              // queue + sp writes visible
        nact = qcnt;
    }

#pragma unroll
    for (int k = 0; k < 4; k++) {
        int i = t + 1024 * k;
        out[2 * i]     = sp[i].x;
        out[2 * i + 1] = sp[i].y;
    }
}

// ---------------- launch ----------------------------------------------------
extern "C" void kernel_launch(void* const* d_in, const int* in_sizes, int n_in,
                              void* d_out, int out_size) {
    const float* pre = (const float*)d_in[0];
    const float* pim = (const float*)d_in[1];
    const float* ore = (const float*)d_in[2];
    const float* oim = (const float*)d_in[3];
    const float* del = (const float*)d_in[4];
    const float* rn  = (const float*)d_in[5];
    const float* tnr = (const float*)d_in[6];
    const float* tni = (const float*)d_in[7];
    float* out = (float*)d_out;

    k_main<<<128, 1024>>>(pre, pim, ore, oim, del, rn, tnr, tni, out);
    k_collide<<<1, 1024>>>(out);
}

// round 9
// speedup vs baseline: 1.0582x; 1.0582x over previous
#include <cuda_runtime.h>
#include <math.h>

#define NPART 4096
#define MAXNB 48
#define HCAP  256     // heavy-queue capacity (overflow spills to light queue)
#define HTHR  16      // candidate count above which a particle is "heavy"

// ---------------- device scratch (no allocations allowed) ----------------
__device__ float2         g_p0[NPART];            // pos + trans (collision input)
__device__ unsigned short g_nb16[NPART * MAXNB];  // candidate lists (uint16 idx, 96B rows)
__device__ int            g_ncnt[NPART];

// ---------------- constants (match reference float32 semantics) ----------
#define PI_F      3.1415927410125732f
#define TWO_PI_F  6.2831854820251465f

__device__ __forceinline__ float wrapf(float diff) {
    // matches: where(diff <= -pi, mod(diff, pi), diff); then -2pi if >= pi
    if (diff <= -PI_F) {
        float m = fmodf(diff, PI_F);       // C fmod: sign of dividend
        if (m < 0.0f) m += PI_F;           // -> pythonic mod in [0, pi)
        diff = m;
    }
    if (diff >= PI_F) diff -= TWO_PI_F;
    return diff;
}

// ---------------- K1: N^2 pair pass + per-particle epilogue ----------------
// One warp per particle. 128 blocks x 32 warps = 4096 particles.
__global__ void __launch_bounds__(1024) k_main(
    const float* __restrict__ pre, const float* __restrict__ pim,
    const float* __restrict__ ore, const float* __restrict__ oim,
    const float* __restrict__ deltas, const float* __restrict__ rotn,
    const float* __restrict__ tnr, const float* __restrict__ tni,
    float* __restrict__ out)
{
    const float RO_RC2 = (float)(2.815e-5 * 2.815e-5);   // (RO+RC)^2
    const float RR2    = (float)(8.0e-6 * 8.0e-6);       // RR^2
    const float NB2    = (float)(2.52e-5 * 2.52e-5);     // (8*RC)^2 candidate radius

    __shared__ float2 spos[NPART];   // 32 KB: whole system
    __shared__ float  swx[32], swy[32];
    __shared__ float2 smean;

    int t    = threadIdx.x;
    int warp = t >> 5;
    int lane = t & 31;

    // stage positions + partial mean sums
    float ax = 0.f, ay = 0.f;
#pragma unroll
    for (int k = 0; k < 4; k++) {
        int idx = t + 1024 * k;
        float x = pre[idx], y = pim[idx];
        spos[idx] = make_float2(x, y);
        ax += x; ay += y;
    }
#pragma unroll
    for (int o = 16; o > 0; o >>= 1) {
        ax += __shfl_down_sync(0xffffffffu, ax, o);
        ay += __shfl_down_sync(0xffffffffu, ay, o);
    }
    if (lane == 0) { swx[warp] = ax; swy[warp] = ay; }
    __syncthreads();
    if (warp == 0) {
        float bx = swx[lane], by = swy[lane];
#pragma unroll
        for (int o = 16; o > 0; o >>= 1) {
            bx += __shfl_down_sync(0xffffffffu, bx, o);
            by += __shfl_down_sync(0xffffffffu, by, o);
        }
        if (lane == 0) smean = make_float2(bx * (1.0f / 4096.0f), by * (1.0f / 4096.0f));
    }
    __syncthreads();

    int i = blockIdx.x * 32 + warp;
    float2 pi_ = spos[i];
    float  orx = __ldg(&ore[i]), ory = __ldg(&oim[i]);

    float osr = 0.f, osi = 0.f, sx = 0.f, sy = 0.f;
    int nr = 0, cnt = 0;
    unsigned lmask = (1u << lane) - 1u;
    const float4* sp4 = reinterpret_cast<const float4*>(spos);

#pragma unroll 4
    for (int jj = lane; jj < NPART / 2; jj += 32) {
        float4 v = sp4[jj];                    // particles 2jj, 2jj+1
        int jA = 2 * jj, jB = 2 * jj + 1;
        float dxA = v.x - pi_.x, dyA = v.y - pi_.y;
        float dxB = v.z - pi_.x, dyB = v.w - pi_.y;
        float d2A = fmaf(dxA, dxA, dyA * dyA);
        float d2B = fmaf(dxB, dxB, dyB * dyB);
        bool roA = (d2A <= RO_RC2), roB = (d2B <= RO_RC2);
        unsigned mro = __ballot_sync(0xffffffffu, roA || roB);
        if (mro) {   // rare branch (~9% of iterations), warp-uniform
            bool nbA = roA && (d2A <= NB2) && (jA != i);
            bool nbB = roB && (d2B <= NB2) && (jB != i);
            unsigned mA = __ballot_sync(0xffffffffu, nbA);
            unsigned mB = __ballot_sync(0xffffffffu, nbB);
            if (nbA) {
                int idx = cnt + __popc(mA & lmask);
                if (idx < MAXNB) g_nb16[i * MAXNB + idx] = (unsigned short)jA;
            }
            cnt += __popc(mA);
            if (nbB) {
                int idx = cnt + __popc(mB & lmask);
                if (idx < MAXNB) g_nb16[i * MAXNB + idx] = (unsigned short)jB;
            }
            cnt += __popc(mB);
            if (roA) {
                float ojx = __ldg(&ore[jA]), ojy = __ldg(&oim[jA]);
                osr += ojx; osi += ojy;
                if (d2A <= RR2 && jA != i) {
                    // |wrap(ang_i-ang_j)| < pi/2  <=>  dot(ori_i, ori_j) > 0
                    if (orx * ojx + ory * ojy > 0.0f) { nr += 1; sx += v.x; sy += v.y; }
                }
            }
            if (roB) {
                float ojx = __ldg(&ore[jB]), ojy = __ldg(&oim[jB]);
                osr += ojx; osi += ojy;
                if (d2B <= RR2 && jB != i) {
                    if (orx * ojx + ory * ojy > 0.0f) { nr += 1; sx += v.z; sy += v.w; }
                }
            }
        }
    }

    // warp reduction
#pragma unroll
    for (int o = 16; o > 0; o >>= 1) {
        osr += __shfl_down_sync(0xffffffffu, osr, o);
        osi += __shfl_down_sync(0xffffffffu, osi, o);
        sx  += __shfl_down_sync(0xffffffffu, sx,  o);
        sy  += __shfl_down_sync(0xffffffffu, sy,  o);
        nr  += __shfl_down_sync(0xffffffffu, nr,  o);
    }

    if (lane == 0) {
        g_ncnt[i] = (cnt < MAXNB) ? cnt : MAXNB;

        float angi = atan2f(ory, orx);
        float2 mean = smean;
        float invn = 1.0f / fmaxf((float)nr, 1.0f);
        float sgn  = (nr > 0) ? 1.0f : 0.0f;
        float Sx = sx * invn - pi_.x * sgn;
        float Sy = sy * invn - pi_.y * sgn;
        float dxr = -Sx, dyr = -Sy;

        float Psx = mean.x - pi_.x;
        float Psy = mean.y - pi_.y;

        float del = deltas[i];
        float cd, sd; sincosf(del, &sd, &cd);
        float lx = Psx * cd - Psy * sd;            // Ps * exp(+i delta)
        float ly = Psx * sd + Psy * cd;
        float rx = Psx * cd + Psy * sd;            // Ps * exp(-i delta)
        float ry = Psy * cd - Psx * sd;

        float no  = fmaxf(sqrtf(osr * osr + osi * osi), 1e-14f);
        float nl  = fmaxf(sqrtf(lx * lx + ly * ly), 1e-14f);
        float nrt = fmaxf(sqrtf(rx * rx + ry * ry), 1e-14f);
        float csl = (lx * osr + ly * osi) / (nl * no);
        float csr = (rx * osr + ry * osi) / (nrt * no);
        float bx = (csl >= csr) ? lx : rx;
        float by = (csl >= csr) ? ly : ry;

        bool hasrep = (dxr * dxr + dyr * dyr) > 0.0f;
        float aa  = hasrep ? atan2f(dyr, dxr) : atan2f(by, bx);
        float att = wrapf(aa - angi);

        float theta = 0.014f * sinf(att)
                    + (rotn[i] * 0.074833147735478508f) * 0.44721359549995793f;
        float cr, sr; sincosf(theta, &sr, &cr);
        float nor = orx * cr - ory * sr;           // new_ori = ori * rot
        float noi = orx * sr + ory * cr;

        float tnx = ((tnr[i] * 0.70710678118654752f) * 1.6733200530681511e-7f)
                    * 0.44721359549995793f;
        float tny = ((tni[i] * 0.70710678118654752f) * 1.6733200530681511e-7f)
                    * 0.44721359549995793f;
        float trx = 1e-7f * orx + tnx;             // DT*VEL*ori + tnoise*sqrt(DT)
        float try_ = 1e-7f * ory + tny;

        g_p0[i] = make_float2(pi_.x + trx, pi_.y + try_);

        out[ 8192 + 2 * i]     = nor;  out[ 8192 + 2 * i + 1] = noi;  // new_ori
        out[16384 + 2 * i]     = osr;  out[16384 + 2 * i + 1] = osi;  // osum
        out[24576 + 2 * i]     = lx;   out[24576 + 2 * i + 1] = ly;   // left
        out[32768 + 2 * i]     = rx;   out[32768 + 2 * i + 1] = ry;   // right
    }
}

// ---------------- K2: collision solve -------------------------------------
// Light particles (cnt<=HTHR): thread-per-particle, MLP-4 neighbor loop.
// Heavy particles (cnt>HTHR): warp-per-particle (breaks the straggler chain).
__global__ void __launch_bounds__(1024) k_collide(float* __restrict__ out) {
    __shared__ float2         sp[NPART];       // 32 KB positions
    __shared__ unsigned short lq[NPART];       // 8 KB  light queue
    __shared__ unsigned short hq[HCAP];        // 512 B heavy queue
    __shared__ float2         hres[HCAP];      // 2 KB  heavy results
    __shared__ unsigned char  hmv[HCAP];       // heavy moved flags
    __shared__ unsigned char  mark[NPART];     // 4 KB epoch stamps
    __shared__ int            nlq, nhq;

    int t = threadIdx.x;
    int warp = t >> 5;
    int lane = t & 31;
    unsigned lmask = (1u << lane) - 1u;

#pragma unroll
    for (int k = 0; k < 4; k++) {
        int i = t + 1024 * k;
        sp[i] = g_p0[i];
        mark[i] = 0;
    }
    if (t < HCAP) hmv[t] = 0;
    if (t == 0) { nlq = 0; nhq = 0; }
    __syncthreads();

    // ---- initial classification: every particle with cnt>0 ----
#pragma unroll
    for (int k = 0; k < 4; k++) {
        int i = t + 1024 * k;
        int c = g_ncnt[i];
        bool heavy = (c > HTHR);
        bool light = (c > 0) && !heavy;
        if (heavy) {
            int s = atomicAdd(&nhq, 1);
            if (s < HCAP) hq[s] = (unsigned short)i;
            else          light = true;               // overflow -> light path
        }
        unsigned mb = __ballot_sync(0xffffffffu, light);
        if (mb) {
            int leader = __ffs(mb) - 1;
            int base = 0;
            if (lane == leader) base = atomicAdd(&nlq, __popc(mb));
            base = __shfl_sync(0xffffffffu, base, leader);
            if (light) lq[base + __popc(mb & lmask)] = (unsigned short)i;
        }
    }
    __syncthreads();

    const float C2  = (float)(6.3e-6 * 6.3e-6);   // (2*RC)^2
    const float TRC = 6.615e-6f;                  // 2.1*RC

    int nl = nlq;
    int nh = (nhq < HCAP) ? nhq : HCAP;

    for (int it = 0; it < 30; it++) {
        bool moved_any = false;
        int   mvi[4]; float mvx[4], mvy[4];
        int nmv = 0;

        // ---- light compute: thread-per-particle, MLP-4 inner ----
        for (int s = t; s < nl; s += 1024) {
            int i = (int)lq[s];
            int c = g_ncnt[i];
            float2 p = sp[i];
            float ax = 0.f, ay = 0.f;
            bool m = false;
            const unsigned* nbp = reinterpret_cast<const unsigned*>(&g_nb16[i * MAXNB]);
            for (int q = 0; q < c; q += 4) {
                unsigned wA = nbp[(q >> 1)];
                unsigned wB = nbp[(q >> 1) + 1];
                int j0 = wA & 4095, j1 = (wA >> 16) & 4095;
                int j2 = wB & 4095, j3 = (wB >> 16) & 4095;
                float2 p0 = sp[j0], p1 = sp[j1], p2 = sp[j2], p3 = sp[j3];
#pragma unroll
                for (int r = 0; r < 4; r++) {
                    if (q + r < c) {
                        float2 pj = (r == 0) ? p0 : (r == 1) ? p1 : (r == 2) ? p2 : p3;
                        float dx = pj.x - p.x;
                        float dy = pj.y - p.y;
                        float d2 = dx * dx + dy * dy;
                        if (d2 <= C2) {
                            float dd = sqrtf(d2);
                            float sc = (TRC - dd) * 0.5f / dd;
                            ax += dx * sc; ay += dy * sc;
                            m = true;
                        }
                    }
                }
            }
            if (m) {
                mvi[nmv] = i; mvx[nmv] = p.x - ax; mvy[nmv] = p.y - ay;
                nmv++; moved_any = true;
            }
        }

        // ---- heavy compute: warp-per-particle ----
        for (int h = warp; h < nh; h += 32) {
            int i = (int)hq[h];
            int c = g_ncnt[i];
            float2 p = sp[i];
            float ax = 0.f, ay = 0.f;
            bool m = false;
            const unsigned short* nb = &g_nb16[i * MAXNB];
            for (int q = lane; q < c; q += 32) {
                float2 pj = sp[nb[q]];
                float dx = pj.x - p.x;
                float dy = pj.y - p.y;
                float d2 = dx * dx + dy * dy;
                if (d2 <= C2) {
                    float dd = sqrtf(d2);
                    float sc = (TRC - dd) * 0.5f / dd;
                    ax += dx * sc; ay += dy * sc;
                    m = true;
                }
            }
#pragma unroll
            for (int o = 16; o > 0; o >>= 1) {
                ax += __shfl_xor_sync(0xffffffffu, ax, o);
                ay += __shfl_xor_sync(0xffffffffu, ay, o);
            }
            m = (__ballot_sync(0xffffffffu, m) != 0u);
            if (lane == 0) {
                hmv[h] = m ? 1 : 0;
                if (m) { hres[h] = make_float2(p.x - ax, p.y - ay); moved_any = true; }
            }
        }

        int tot = __syncthreads_count(moved_any ? 1 : 0);   // all sp reads done
        if (tot == 0) break;          // no collisions anywhere -> fixed point (== ref cont)

        // ---- apply + stamp ----
        unsigned char epn = (unsigned char)(it + 1);
        for (int r = 0; r < nmv; r++) {
            int i = mvi[r];
            sp[i] = make_float2(mvx[r], mvy[r]);
            mark[i] = epn;
            int c = g_ncnt[i];
            const unsigned short* nb = &g_nb16[i * MAXNB];
            for (int q = 0; q < c; q++) mark[nb[q]] = epn;   // benign same-value races
        }
        for (int h = t; h < nh; h += 1024) {
            if (hmv[h]) {
                hmv[h] = 0;
                int i = (int)hq[h];
                sp[i] = hres[h];
                mark[i] = epn;
                int c = g_ncnt[i];
                const unsigned short* nb = &g_nb16[i * MAXNB];
                for (int q = 0; q < c; q++) mark[nb[q]] = epn;
            }
        }
        if (t == 0) { nlq = 0; nhq = 0; }
        __syncthreads();              // marks + counter reset visible

        // ---- compaction: rebuild queues from stamps ----
#pragma unroll
        for (int k = 0; k < 4; k++) {
            int i = t + 1024 * k;
            bool act = (mark[i] == epn);
            int c = act ? g_ncnt[i] : 0;
            bool heavy = act && (c > HTHR);
            bool light = act && (c > 0) && !heavy;
            if (heavy) {
                int s = atomicAdd(&nhq, 1);
                if (s < HCAP) hq[s] = (unsigned short)i;
                else          light = true;
            }
            unsigned mb = __ballot_sync(0xffffffffu, light);
            if (mb) {
                int leader = __ffs(mb) - 1;
                int base = 0;
                if (lane == leader) base = atomicAdd(&nlq, __popc(mb));
                base = __shfl_sync(0xffffffffu, base, leader);
                if (light) lq[base + __popc(mb & lmask)] = (unsigned short)i;
            }
        }
        __syncthreads();              // queues + sp writes visible
        nl = nlq;
        nh = (nhq < HCAP) ? nhq : HCAP;
    }

#pragma unroll
    for (int k = 0; k < 4; k++) {
        int i = t + 1024 * k;
        out[2 * i]     = sp[i].x;
        out[2 * i + 1] = sp[i].y;
    }
}

// ---------------- launch ----------------------------------------------------
extern "C" void kernel_launch(void* const* d_in, const int* in_sizes, int n_in,
                              void* d_out, int out_size) {
    const float* pre = (const float*)d_in[0];
    const float* pim = (const float*)d_in[1];
    const float* ore = (const float*)d_in[2];
    const float* oim = (const float*)d_in[3];
    const float* del = (const float*)d_in[4];
    const float* rn  = (const float*)d_in[5];
    const float* tnr = (const float*)d_in[6];
    const float* tni = (const float*)d_in[7];
    float* out = (float*)d_out;

    k_main<<<128, 1024>>>(pre, pim, ore, oim, del, rn, tnr, tni, out);
    k_collide<<<1, 1024>>>(out);
}